// round 2
// baseline (speedup 1.0000x reference)
#include <cuda_runtime.h>
#include <math.h>

#define VV 4
#define NN 2048
#define DD 128
#define KK 10
#define NPAIR 12   // off-diagonal (p,q) pairs

// ---------------- scratch (no allocs allowed) ----------------
__device__ float g_Q[VV * NN * DD];
__device__ float g_K[VV * NN * DD];
__device__ float g_V[VV * NN * DD];
__device__ int   g_idx[NPAIR * NN * KK];
__device__ float g_meanV[VV * DD];

// ---------------- projection GEMMs: out = X @ W^T ----------------
// grid (32 row-tiles, 12 = v*3+mat), block 256.
// Each block: 64 rows x 128 cols output tile, register-blocked 8x4 per thread.
__global__ __launch_bounds__(256) void proj_kernel(
    const float* __restrict__ aligned,
    const float* __restrict__ WQ,
    const float* __restrict__ WK,
    const float* __restrict__ WV)
{
    int tile = blockIdx.x;
    int vm   = blockIdx.y;
    int v = vm / 3, mat = vm % 3;
    const float* W = (mat == 0 ? WQ : (mat == 1 ? WK : WV)) + (size_t)v * DD * DD;
    float* Out = (mat == 0 ? g_Q : (mat == 1 ? g_K : g_V))
                 + (size_t)v * NN * DD + (size_t)tile * 64 * DD;
    const float* X = aligned + (size_t)v * NN * DD + (size_t)tile * 64 * DD;

    __shared__ float Xs[64][16];     // 4 KB
    __shared__ float Ws[16][132];    // padded rows (528 B, 16B aligned)

    int tid = threadIdx.x;
    int ty = tid >> 5, tx = tid & 31;   // warp = ty, lane = tx

    float acc[8][4];
#pragma unroll
    for (int i = 0; i < 8; ++i)
#pragma unroll
        for (int c = 0; c < 4; ++c) acc[i][c] = 0.f;

    for (int d0 = 0; d0 < DD; d0 += 16) {
        // X tile 64x16: one float4 per thread
        {
            int r = tid >> 2, f = tid & 3;
            float4 xv = *(const float4*)(X + (size_t)r * DD + d0 + f * 4);
            *(float4*)&Xs[r][f * 4] = xv;
        }
        // W chunk 128x16, stored transposed into Ws[dd][e]
#pragma unroll
        for (int j = 0; j < 2; ++j) {
            int lin = tid * 2 + j;
            int e = lin >> 2, f = lin & 3;
            float4 wv = *(const float4*)(W + (size_t)e * DD + d0 + f * 4);
            Ws[f * 4 + 0][e] = wv.x;
            Ws[f * 4 + 1][e] = wv.y;
            Ws[f * 4 + 2][e] = wv.z;
            Ws[f * 4 + 3][e] = wv.w;
        }
        __syncthreads();
#pragma unroll
        for (int dd = 0; dd < 16; ++dd) {
            float4 b = *(const float4*)&Ws[dd][tx * 4];
#pragma unroll
            for (int i = 0; i < 8; ++i) {
                float a = Xs[ty * 8 + i][dd];   // warp-uniform broadcast
                acc[i][0] += a * b.x;
                acc[i][1] += a * b.y;
                acc[i][2] += a * b.z;
                acc[i][3] += a * b.w;
            }
        }
        __syncthreads();
    }
#pragma unroll
    for (int i = 0; i < 8; ++i) {
        float4 o = make_float4(acc[i][0], acc[i][1], acc[i][2], acc[i][3]);
        *(float4*)(Out + (size_t)(ty * 8 + i) * DD + tx * 4) = o;
    }
}

// ---------------- meanV: column sums of g_V per view ----------------
__global__ void meanv_kernel()
{
    int p = blockIdx.x >> 4;
    int chunk = blockIdx.x & 15;
    int d = threadIdx.x;
    const float* base = g_V + ((size_t)p * NN + (size_t)chunk * 128) * DD + d;
    float s = 0.f;
#pragma unroll 8
    for (int r = 0; r < 128; ++r) s += base[(size_t)r * DD];
    atomicAdd(&g_meanV[p * DD + d], s);
}

// ---------------- top-10 per row, EXACT jax tie-breaking ----------------
// key = (monotonic float bits << 32) | (NN-1-index): higher key = higher value,
// ties -> lower index (matches lax.top_k). Keys are unique per row, so the
// warp merge is fully deterministic (no double-win on duplicate values).
__device__ __forceinline__ unsigned long long tk_key(float x, int m)
{
    unsigned int fb = __float_as_uint(x);
    fb = (fb & 0x80000000u) ? ~fb : (fb | 0x80000000u);  // total order on floats
    return ((unsigned long long)fb << 32) | (unsigned int)(NN - 1 - m);
}

__global__ __launch_bounds__(256) void topk_kernel(const float* __restrict__ C)
{
    int warp = threadIdx.x >> 5, lane = threadIdx.x & 31;
    int rowg = blockIdx.x * 8 + warp;          // 0 .. 24575
    int pair = rowg / NN, n = rowg % NN;
    int p = pair / 3, qm = pair % 3;
    int q = qm + (qm >= p ? 1 : 0);
    const float* rowp = C + (((size_t)p * VV + q) * NN + n) * (size_t)NN;

    unsigned long long tk[KK];
#pragma unroll
    for (int j = 0; j < KK; ++j) tk[j] = 0ull;

#pragma unroll 4
    for (int i = 0; i < NN / 32; ++i) {
        int m = lane + (i << 5);
        unsigned long long k = tk_key(__ldcs(rowp + m), m);
        if (k > tk[KK - 1]) {
            tk[KK - 1] = k;
#pragma unroll
            for (int j = KK - 1; j > 0; --j) {
                if (tk[j] > tk[j - 1]) {
                    unsigned long long t = tk[j]; tk[j] = tk[j - 1]; tk[j - 1] = t;
                }
            }
        }
    }

    __shared__ unsigned long long sk[8][32][KK];   // 20 KB
#pragma unroll
    for (int j = 0; j < KK; ++j) sk[warp][lane][j] = tk[j];
    __syncwarp();

    int ptr = 0;
    int* outp = g_idx + (size_t)rowg * KK;
#pragma unroll
    for (int r = 0; r < KK; ++r) {
        unsigned long long cand = (ptr < KK) ? sk[warp][lane][ptr] : 0ull;
        unsigned long long bk = cand;
#pragma unroll
        for (int off = 16; off > 0; off >>= 1) {
            unsigned long long ok = __shfl_xor_sync(0xffffffffu, bk, off);
            if (ok > bk) bk = ok;
        }
        if (cand == bk) ptr++;          // unique keys -> exactly one winner
        if (lane == 0) outp[r] = NN - 1 - (int)(bk & 0xffffffffu);
    }
}

// ---------------- gather + sparse softmax + aggregate ----------------
// grid (N, V), block 128 (thread = output channel d).
__global__ __launch_bounds__(128) void gather_kernel(float* __restrict__ out)
{
    int n = blockIdx.x, p = blockIdx.y;
    int tid = threadIdx.x;
    int w = tid >> 5, lane = tid & 31;

    __shared__ float qs[DD];
    __shared__ int   sidx[32];
    __shared__ float sc[32];
    __shared__ float sw[32];
    __shared__ float smax[4], ssum[4];

    qs[tid] = g_Q[((size_t)p * NN + n) * DD + tid];
    if (tid < 3 * KK) {
        int qm = tid / KK, k = tid % KK;
        int pair = p * 3 + qm;
        sidx[tid] = g_idx[((size_t)pair * NN + n) * KK + k];
    }
    __syncthreads();

    // 30 dot products: Q[p,n] . K[q, idx]  (warp per dot, round-robin)
    for (int t = w; t < 3 * KK; t += 4) {
        int qm = t / KK;
        int q = qm + (qm >= p ? 1 : 0);
        int m = sidx[t];
        const float* kr = g_K + ((size_t)q * NN + m) * DD;
        float s = 0.f;
#pragma unroll
        for (int j = 0; j < 4; ++j)
            s += qs[lane + 32 * j] * __ldg(kr + lane + 32 * j);
#pragma unroll
        for (int off = 16; off > 0; off >>= 1)
            s += __shfl_xor_sync(0xffffffffu, s, off);
        if (lane == 0) sc[t] = s * 0.08838834764831845f;   // 1/sqrt(128)
    }
    __syncthreads();

    // softmax over each q's 10 scores (exact: masked entries underflow to 0)
    if (tid < 3) {
        float mx = -3.4e38f;
#pragma unroll
        for (int k = 0; k < KK; ++k) mx = fmaxf(mx, sc[tid * KK + k]);
        smax[tid] = mx;
    }
    __syncthreads();
    if (tid < 3 * KK) sc[tid] = expf(sc[tid] - smax[tid / KK]);
    __syncthreads();
    if (tid < 3) {
        float su = 0.f;
#pragma unroll
        for (int k = 0; k < KK; ++k) su += sc[tid * KK + k];
        ssum[tid] = su;
    }
    __syncthreads();
    if (tid < 3 * KK) sw[tid] = sc[tid] / ssum[tid / KK];
    __syncthreads();

    // diagonal block: uniform softmax over all-masked row -> mean of V[p]
    float acc = g_meanV[p * DD + tid] * (1.0f / NN);
#pragma unroll
    for (int t = 0; t < 3 * KK; ++t) {
        int qm = t / KK;
        int q = qm + (qm >= p ? 1 : 0);
        acc += sw[t] * __ldg(g_V + ((size_t)q * NN + sidx[t]) * DD + tid);
    }
    out[((size_t)p * NN + n) * DD + tid] = acc;
}

// ---------------- launch ----------------
extern "C" void kernel_launch(void* const* d_in, const int* in_sizes, int n_in,
                              void* d_out, int out_size)
{
    const float* aligned = (const float*)d_in[0];
    const float* C       = (const float*)d_in[1];
    const float* WQ      = (const float*)d_in[2];
    const float* WK      = (const float*)d_in[3];
    const float* WV      = (const float*)d_in[4];
    float* out = (float*)d_out;

    void* meanp = nullptr;
    cudaGetSymbolAddress(&meanp, g_meanV);

    proj_kernel<<<dim3(32, 12), 256>>>(aligned, WQ, WK, WV);
    cudaMemsetAsync(meanp, 0, VV * DD * sizeof(float));
    meanv_kernel<<<64, 128>>>();
    topk_kernel<<<NPAIR * NN / 8, 256>>>(C);
    gather_kernel<<<dim3(NN, VV), 128>>>(out);
}

// round 3
// speedup vs baseline: 1.7453x; 1.7453x over previous
#include <cuda_runtime.h>
#include <math.h>

#define VV 4
#define NN 2048
#define DD 128
#define KK 10
#define NPAIR 12   // off-diagonal (p,q) pairs
#define PROJ_BLOCKS 384
#define TOPK_BLOCKS 3072
#define CAND_CAP 64

// ---------------- scratch (no allocs allowed) ----------------
__device__ float g_Q[VV * NN * DD];
__device__ float g_K[VV * NN * DD];
__device__ float g_V[VV * NN * DD];
__device__ int   g_idx[NPAIR * NN * KK];
__device__ float g_meanV[VV * DD];

// total-order 64-bit key: higher value wins; ties -> lower index (matches lax.top_k)
__device__ __forceinline__ unsigned long long tk_key(float x, int m)
{
    unsigned int mb = __float_as_uint(x);
    mb ^= ((unsigned int)((int)mb >> 31)) | 0x80000000u;
    return ((unsigned long long)mb << 32) | (unsigned int)(NN - 1 - m);
}

__device__ __forceinline__ unsigned long long wmax64(unsigned long long k)
{
#pragma unroll
    for (int off = 16; off > 0; off >>= 1) {
        unsigned long long o = __shfl_xor_sync(0xffffffffu, k, off);
        if (o > k) k = o;
    }
    return k;
}

// ================= fused proj + topk =================
// role interleave: bid % 9 == 0 -> proj (384 blocks), else topk (3072 blocks)
__global__ __launch_bounds__(256, 2) void proj_topk_kernel(
    const float* __restrict__ aligned,
    const float* __restrict__ WQ,
    const float* __restrict__ WK,
    const float* __restrict__ WV,
    const float* __restrict__ C)
{
    int bid = blockIdx.x;
    int tid = threadIdx.x;

    if (bid % 9 == 0) {
        // ---------------- projection GEMM block ----------------
        int pb = bid / 9;                 // 0..383
        int tile = pb & 31;
        int vm   = pb >> 5;               // 0..11
        int v = vm / 3, mat = vm % 3;
        const float* W = (mat == 0 ? WQ : (mat == 1 ? WK : WV)) + (size_t)v * DD * DD;
        float* Out = (mat == 0 ? g_Q : (mat == 1 ? g_K : g_V))
                     + (size_t)v * NN * DD + (size_t)tile * 64 * DD;
        const float* X = aligned + (size_t)v * NN * DD + (size_t)tile * 64 * DD;

        __shared__ float Xs[64][16];
        __shared__ float Ws[16][132];

        int ty = tid >> 5, tx = tid & 31;
        float acc[8][4];
#pragma unroll
        for (int i = 0; i < 8; ++i)
#pragma unroll
            for (int c = 0; c < 4; ++c) acc[i][c] = 0.f;

        for (int d0 = 0; d0 < DD; d0 += 16) {
            {
                int r = tid >> 2, f = tid & 3;
                float4 xv = *(const float4*)(X + (size_t)r * DD + d0 + f * 4);
                *(float4*)&Xs[r][f * 4] = xv;
            }
#pragma unroll
            for (int j = 0; j < 2; ++j) {
                int lin = tid * 2 + j;
                int e = lin >> 2, f = lin & 3;
                float4 wv = *(const float4*)(W + (size_t)e * DD + d0 + f * 4);
                Ws[f * 4 + 0][e] = wv.x;
                Ws[f * 4 + 1][e] = wv.y;
                Ws[f * 4 + 2][e] = wv.z;
                Ws[f * 4 + 3][e] = wv.w;
            }
            __syncthreads();
#pragma unroll
            for (int dd = 0; dd < 16; ++dd) {
                float4 b = *(const float4*)&Ws[dd][tx * 4];
#pragma unroll
                for (int i = 0; i < 8; ++i) {
                    float a = Xs[ty * 8 + i][dd];
                    acc[i][0] += a * b.x;
                    acc[i][1] += a * b.y;
                    acc[i][2] += a * b.z;
                    acc[i][3] += a * b.w;
                }
            }
            __syncthreads();
        }
#pragma unroll
        for (int i = 0; i < 8; ++i) {
            float4 o = make_float4(acc[i][0], acc[i][1], acc[i][2], acc[i][3]);
            *(float4*)(Out + (size_t)(ty * 8 + i) * DD + tx * 4) = o;
        }
        return;
    }

    // ---------------- topk block: 8 warps, one row each ----------------
    int tb = bid - bid / 9 - 1;           // 0..3071
    int warp = tid >> 5, lane = tid & 31;
    int rowg = tb * 8 + warp;             // 0..24575
    int pair = rowg / NN, n = rowg % NN;
    int p = pair / 3, qm = pair % 3;
    int q = qm + (qm >= p ? 1 : 0);
    const float4* rowp4 = (const float4*)
        (C + (((size_t)p * VV + q) * NN + n) * (size_t)NN);

    __shared__ unsigned long long cbuf[8][CAND_CAP];  // 4 KB

    // pass 1: register-resident row + per-lane float max (lowest index on tie)
    float x[64];
    float mx = -3.4e38f;
    int   mi = 0;
#pragma unroll
    for (int i = 0; i < 16; ++i) {
        float4 v = __ldcs(rowp4 + lane + (i << 5));
        x[i * 4 + 0] = v.x; x[i * 4 + 1] = v.y;
        x[i * 4 + 2] = v.z; x[i * 4 + 3] = v.w;
        int mbase = (lane + (i << 5)) << 2;
        if (v.x > mx) { mx = v.x; mi = mbase; }
        if (v.y > mx) { mx = v.y; mi = mbase + 1; }
        if (v.z > mx) { mx = v.z; mi = mbase + 2; }
        if (v.w > mx) { mx = v.w; mi = mbase + 3; }
    }

    // tau = 10th-largest lane-max key (10 extraction rounds)
    unsigned long long cur = tk_key(mx, mi);
    unsigned long long tau = 0;
#pragma unroll
    for (int r = 0; r < KK; ++r) {
        unsigned long long m = wmax64(cur);
        if (cur == m) cur = 0ull;     // unique keys -> exactly one lane
        tau = m;
    }

    // compact candidates (key >= tau) into smem
    int base = 0;
    unsigned int lmask = (1u << lane) - 1u;
#pragma unroll
    for (int e = 0; e < 64; ++e) {
        int m = (((e >> 2) << 5) + lane) * 4 + (e & 3);
        unsigned long long k = tk_key(x[e], m);
        bool pass = (k >= tau);
        unsigned int bal = __ballot_sync(0xffffffffu, pass);
        if (pass) {
            int pos = base + __popc(bal & lmask);
            cbuf[warp][pos < CAND_CAP ? pos : (CAND_CAP - 1)] = k;
        }
        base += __popc(bal);
    }
    __syncwarp();

    int* outp = g_idx + (size_t)rowg * KK;
    if (base <= CAND_CAP) {
        unsigned long long a = (lane < base) ? cbuf[warp][lane] : 0ull;
        unsigned long long b = (lane + 32 < base) ? cbuf[warp][lane + 32] : 0ull;
        unsigned long long cand = (a > b) ? a : b;
#pragma unroll
        for (int r = 0; r < KK; ++r) {
            unsigned long long m = wmax64(cand);
            if (lane == 0) outp[r] = NN - 1 - (int)(m & 0xffffffffu);
            if (cand == m) {
                if (a == m) a = 0ull; else b = 0ull;
                cand = (a > b) ? a : b;
            }
        }
    } else {
        // exact fallback: bounded rescan extraction (essentially never taken)
        unsigned long long bound = ~0ull;
        for (int r = 0; r < KK; ++r) {
            unsigned long long cand = 0ull;
#pragma unroll
            for (int e = 0; e < 64; ++e) {
                int m = (((e >> 2) << 5) + lane) * 4 + (e & 3);
                unsigned long long k = tk_key(x[e], m);
                if (k < bound && k > cand) cand = k;
            }
            unsigned long long m = wmax64(cand);
            if (lane == 0) outp[r] = NN - 1 - (int)(m & 0xffffffffu);
            bound = m;
        }
    }
}

// ---------------- meanV: column sums of g_V per view ----------------
__global__ void meanv_kernel()
{
    int p = blockIdx.x >> 4;
    int chunk = blockIdx.x & 15;
    int d = threadIdx.x;
    const float* base = g_V + ((size_t)p * NN + (size_t)chunk * 128) * DD + d;
    float s = 0.f;
#pragma unroll 8
    for (int r = 0; r < 128; ++r) s += base[(size_t)r * DD];
    atomicAdd(&g_meanV[p * DD + d], s);
}

// ---------------- gather + sparse softmax + aggregate ----------------
__global__ __launch_bounds__(128) void gather_kernel(float* __restrict__ out)
{
    int n = blockIdx.x, p = blockIdx.y;
    int tid = threadIdx.x;
    int w = tid >> 5, lane = tid & 31;

    __shared__ float qs[DD];
    __shared__ int   sidx[32];
    __shared__ float sc[32];
    __shared__ float sw[32];
    __shared__ float smax[4], ssum[4];

    qs[tid] = g_Q[((size_t)p * NN + n) * DD + tid];
    if (tid < 3 * KK) {
        int qm = tid / KK, k = tid % KK;
        int pair = p * 3 + qm;
        sidx[tid] = g_idx[((size_t)pair * NN + n) * KK + k];
    }
    __syncthreads();

    for (int t = w; t < 3 * KK; t += 4) {
        int qm = t / KK;
        int q = qm + (qm >= p ? 1 : 0);
        int m = sidx[t];
        const float* kr = g_K + ((size_t)q * NN + m) * DD;
        float s = 0.f;
#pragma unroll
        for (int j = 0; j < 4; ++j)
            s += qs[lane + 32 * j] * __ldg(kr + lane + 32 * j);
#pragma unroll
        for (int off = 16; off > 0; off >>= 1)
            s += __shfl_xor_sync(0xffffffffu, s, off);
        if (lane == 0) sc[t] = s * 0.08838834764831845f;
    }
    __syncthreads();

    if (tid < 3) {
        float m2 = -3.4e38f;
#pragma unroll
        for (int k = 0; k < KK; ++k) m2 = fmaxf(m2, sc[tid * KK + k]);
        smax[tid] = m2;
    }
    __syncthreads();
    if (tid < 3 * KK) sc[tid] = expf(sc[tid] - smax[tid / KK]);
    __syncthreads();
    if (tid < 3) {
        float su = 0.f;
#pragma unroll
        for (int k = 0; k < KK; ++k) su += sc[tid * KK + k];
        ssum[tid] = su;
    }
    __syncthreads();
    if (tid < 3 * KK) sw[tid] = sc[tid] / ssum[tid / KK];
    __syncthreads();

    float acc = g_meanV[p * DD + tid] * (1.0f / NN);
#pragma unroll
    for (int t = 0; t < 3 * KK; ++t) {
        int qm = t / KK;
        int q = qm + (qm >= p ? 1 : 0);
        acc += sw[t] * __ldg(g_V + ((size_t)q * NN + sidx[t]) * DD + tid);
    }
    out[((size_t)p * NN + n) * DD + tid] = acc;
}

// ---------------- launch ----------------
extern "C" void kernel_launch(void* const* d_in, const int* in_sizes, int n_in,
                              void* d_out, int out_size)
{
    const float* aligned = (const float*)d_in[0];
    const float* C       = (const float*)d_in[1];
    const float* WQ      = (const float*)d_in[2];
    const float* WK      = (const float*)d_in[3];
    const float* WV      = (const float*)d_in[4];
    float* out = (float*)d_out;

    void* meanp = nullptr;
    cudaGetSymbolAddress(&meanp, g_meanV);

    proj_topk_kernel<<<PROJ_BLOCKS + TOPK_BLOCKS, 256>>>(aligned, WQ, WK, WV, C);
    cudaMemsetAsync(meanp, 0, VV * DD * sizeof(float));
    meanv_kernel<<<64, 128>>>();
    gather_kernel<<<dim3(NN, VV), 128>>>(out);
}

// round 4
// speedup vs baseline: 2.5166x; 1.4420x over previous
#include <cuda_runtime.h>
#include <math.h>

#define VV 4
#define NN 2048
#define DD 128
#define KK 10
#define NPAIR 12
#define PROJ_BLOCKS 384
#define TOPK_BLOCKS 3072
#define CAND_CAP 64

// ---------------- scratch (no allocs allowed) ----------------
__device__ float g_Q[VV * NN * DD];
__device__ float g_K[VV * NN * DD];
__device__ float g_V[VV * NN * DD];
__device__ int   g_idx[NPAIR * NN * KK];
__device__ float g_meanV[VV * DD];

// total-order 64-bit key: higher value wins; ties -> lower index (matches lax.top_k)
__device__ __forceinline__ unsigned long long tk_key(float x, int m)
{
    unsigned int mb = __float_as_uint(x);
    mb ^= ((unsigned int)((int)mb >> 31)) | 0x80000000u;
    return ((unsigned long long)mb << 32) | (unsigned int)(NN - 1 - m);
}

__device__ __forceinline__ unsigned long long wmax64(unsigned long long k)
{
#pragma unroll
    for (int off = 16; off > 0; off >>= 1) {
        unsigned long long o = __shfl_xor_sync(0xffffffffu, k, off);
        if (o > k) k = o;
    }
    return k;
}

// ================= fused proj (+meanV) + topk =================
// role interleave: bid % 9 == 0 -> proj (384 blocks), else topk (3072 blocks)
__global__ __launch_bounds__(256, 4) void proj_topk_kernel(
    const float* __restrict__ aligned,
    const float* __restrict__ WQ,
    const float* __restrict__ WK,
    const float* __restrict__ WV,
    const float* __restrict__ C)
{
    int bid = blockIdx.x;
    int tid = threadIdx.x;

    if (bid % 9 == 0) {
        // ---------------- projection GEMM block ----------------
        int pb = bid / 9;                 // 0..383
        int tile = pb & 31;
        int vm   = pb >> 5;               // 0..11
        int v = vm / 3, mat = vm % 3;
        const float* W = (mat == 0 ? WQ : (mat == 1 ? WK : WV)) + (size_t)v * DD * DD;
        float* Out = (mat == 0 ? g_Q : (mat == 1 ? g_K : g_V))
                     + (size_t)v * NN * DD + (size_t)tile * 64 * DD;
        const float* X = aligned + (size_t)v * NN * DD + (size_t)tile * 64 * DD;

        __shared__ float Xs[64][16];
        __shared__ float Ws[16][132];

        int ty = tid >> 5, tx = tid & 31;
        float acc[8][4];
#pragma unroll
        for (int i = 0; i < 8; ++i)
#pragma unroll
            for (int c = 0; c < 4; ++c) acc[i][c] = 0.f;

        for (int d0 = 0; d0 < DD; d0 += 16) {
            {
                int r = tid >> 2, f = tid & 3;
                float4 xv = *(const float4*)(X + (size_t)r * DD + d0 + f * 4);
                *(float4*)&Xs[r][f * 4] = xv;
            }
#pragma unroll
            for (int j = 0; j < 2; ++j) {
                int lin = tid * 2 + j;
                int e = lin >> 2, f = lin & 3;
                float4 wv = *(const float4*)(W + (size_t)e * DD + d0 + f * 4);
                Ws[f * 4 + 0][e] = wv.x;
                Ws[f * 4 + 1][e] = wv.y;
                Ws[f * 4 + 2][e] = wv.z;
                Ws[f * 4 + 3][e] = wv.w;
            }
            __syncthreads();
#pragma unroll
            for (int dd = 0; dd < 16; ++dd) {
                float4 b = *(const float4*)&Ws[dd][tx * 4];
#pragma unroll
                for (int i = 0; i < 8; ++i) {
                    float a = Xs[ty * 8 + i][dd];
                    acc[i][0] += a * b.x;
                    acc[i][1] += a * b.y;
                    acc[i][2] += a * b.z;
                    acc[i][3] += a * b.w;
                }
            }
            __syncthreads();
        }
#pragma unroll
        for (int i = 0; i < 8; ++i) {
            float4 o = make_float4(acc[i][0], acc[i][1], acc[i][2], acc[i][3]);
            *(float4*)(Out + (size_t)(ty * 8 + i) * DD + tx * 4) = o;
        }
        if (mat == 2) {
            // fused meanV: per-thread column partial over this tile's 8 rows
#pragma unroll
            for (int c = 0; c < 4; ++c) {
                float s = 0.f;
#pragma unroll
                for (int i = 0; i < 8; ++i) s += acc[i][c];
                atomicAdd(&g_meanV[v * DD + tx * 4 + c], s);
            }
        }
        return;
    }

    // ---------------- topk block: 8 warps, one row each ----------------
    int tb = bid - bid / 9 - 1;           // 0..3071
    int warp = tid >> 5, lane = tid & 31;
    int rowg = tb * 8 + warp;             // 0..24575
    int pair = rowg / NN, n = rowg % NN;
    int p = pair / 3, qm = pair % 3;
    int q = qm + (qm >= p ? 1 : 0);
    const float4* rowp4 = (const float4*)
        (C + (((size_t)p * VV + q) * NN + n) * (size_t)NN);

    __shared__ unsigned long long cbuf[8][CAND_CAP];  // 4 KB

    // pass 1: per-lane float max only (no indices, no keys)
    float mx = -3.4e38f;
#pragma unroll
    for (int i = 0; i < 16; ++i) {
        float4 v = rowp4[lane + (i << 5)];
        mx = fmaxf(mx, fmaxf(fmaxf(v.x, v.y), fmaxf(v.z, v.w)));
    }

    // tau = (<=10th)-largest lane max. Duplicate lane-maxes may retire in
    // groups -> tau only gets SMALLER -> more candidates -> still exact.
    float cur = mx;
    float tau = 0.f;
#pragma unroll
    for (int r = 0; r < KK; ++r) {
        float m = cur;
#pragma unroll
        for (int off = 16; off > 0; off >>= 1)
            m = fmaxf(m, __shfl_xor_sync(0xffffffffu, m, off));
        if (cur == m) cur = -3.4e38f;
        tau = m;
    }

    // pass 2: reload row (L1/L2 hit), compact candidates >= tau
    int base = 0;
    unsigned int lmask = (1u << lane) - 1u;
#pragma unroll
    for (int i = 0; i < 16; ++i) {
        float4 v = __ldcs(rowp4 + lane + (i << 5));
        int mb = (lane + (i << 5)) << 2;
        float e[4] = {v.x, v.y, v.z, v.w};
#pragma unroll
        for (int c = 0; c < 4; ++c) {
            bool pass = (e[c] >= tau);
            unsigned int bal = __ballot_sync(0xffffffffu, pass);
            if (pass) {
                int pos = base + __popc(bal & lmask);
                if (pos < CAND_CAP) cbuf[warp][pos] = tk_key(e[c], mb + c);
            }
            base += __popc(bal);
        }
    }
    __syncwarp();

    int* outp = g_idx + (size_t)rowg * KK;
    if (base <= CAND_CAP) {
        unsigned long long a = (lane < base) ? cbuf[warp][lane] : 0ull;
        unsigned long long b = (lane + 32 < base) ? cbuf[warp][lane + 32] : 0ull;
        unsigned long long cand = (a > b) ? a : b;
#pragma unroll
        for (int r = 0; r < KK; ++r) {
            unsigned long long m = wmax64(cand);
            if (lane == 0) outp[r] = NN - 1 - (int)(m & 0xffffffffu);
            if (cand == m) {
                if (a == m) a = 0ull; else b = 0ull;
                cand = (a > b) ? a : b;
            }
        }
    } else {
        // exact fallback: bounded rescan extraction (pathological ties only)
        unsigned long long bound = ~0ull;
        for (int r = 0; r < KK; ++r) {
            unsigned long long candk = 0ull;
            for (int i = 0; i < 16; ++i) {
                float4 v = rowp4[lane + (i << 5)];
                int mb = (lane + (i << 5)) << 2;
                unsigned long long k;
                k = tk_key(v.x, mb + 0); if (k < bound && k > candk) candk = k;
                k = tk_key(v.y, mb + 1); if (k < bound && k > candk) candk = k;
                k = tk_key(v.z, mb + 2); if (k < bound && k > candk) candk = k;
                k = tk_key(v.w, mb + 3); if (k < bound && k > candk) candk = k;
            }
            unsigned long long m = wmax64(candk);
            if (lane == 0) outp[r] = NN - 1 - (int)(m & 0xffffffffu);
            bound = m;
        }
    }
}

// ---------------- gather + sparse softmax + aggregate ----------------
__global__ __launch_bounds__(128) void gather_kernel(float* __restrict__ out)
{
    int n = blockIdx.x, p = blockIdx.y;
    int tid = threadIdx.x;
    int w = tid >> 5, lane = tid & 31;

    __shared__ float qs[DD];
    __shared__ int   sidx[32];
    __shared__ float sc[32];
    __shared__ float sw[32];
    __shared__ float smax[4], ssum[4];

    qs[tid] = g_Q[((size_t)p * NN + n) * DD + tid];
    if (tid < 3 * KK) {
        int qm = tid / KK, k = tid % KK;
        int pair = p * 3 + qm;
        sidx[tid] = g_idx[((size_t)pair * NN + n) * KK + k];
    }
    __syncthreads();

    for (int t = w; t < 3 * KK; t += 4) {
        int qm = t / KK;
        int q = qm + (qm >= p ? 1 : 0);
        int m = sidx[t];
        const float* kr = g_K + ((size_t)q * NN + m) * DD;
        float s = 0.f;
#pragma unroll
        for (int j = 0; j < 4; ++j)
            s += qs[lane + 32 * j] * __ldg(kr + lane + 32 * j);
#pragma unroll
        for (int off = 16; off > 0; off >>= 1)
            s += __shfl_xor_sync(0xffffffffu, s, off);
        if (lane == 0) sc[t] = s * 0.08838834764831845f;
    }
    __syncthreads();

    if (tid < 3) {
        float m2 = -3.4e38f;
#pragma unroll
        for (int k = 0; k < KK; ++k) m2 = fmaxf(m2, sc[tid * KK + k]);
        smax[tid] = m2;
    }
    __syncthreads();
    if (tid < 3 * KK) sc[tid] = expf(sc[tid] - smax[tid / KK]);
    __syncthreads();
    if (tid < 3) {
        float su = 0.f;
#pragma unroll
        for (int k = 0; k < KK; ++k) su += sc[tid * KK + k];
        ssum[tid] = su;
    }
    __syncthreads();
    if (tid < 3 * KK) sw[tid] = sc[tid] / ssum[tid / KK];
    __syncthreads();

    float acc = g_meanV[p * DD + tid] * (1.0f / NN);
#pragma unroll
    for (int t = 0; t < 3 * KK; ++t) {
        int qm = t / KK;
        int q = qm + (qm >= p ? 1 : 0);
        acc += sw[t] * __ldg(g_V + ((size_t)q * NN + sidx[t]) * DD + tid);
    }
    out[((size_t)p * NN + n) * DD + tid] = acc;
}

// ---------------- launch ----------------
extern "C" void kernel_launch(void* const* d_in, const int* in_sizes, int n_in,
                              void* d_out, int out_size)
{
    const float* aligned = (const float*)d_in[0];
    const float* C       = (const float*)d_in[1];
    const float* WQ      = (const float*)d_in[2];
    const float* WK      = (const float*)d_in[3];
    const float* WV      = (const float*)d_in[4];
    float* out = (float*)d_out;

    void* meanp = nullptr;
    cudaGetSymbolAddress(&meanp, g_meanV);

    cudaMemsetAsync(meanp, 0, VV * DD * sizeof(float));
    proj_topk_kernel<<<PROJ_BLOCKS + TOPK_BLOCKS, 256>>>(aligned, WQ, WK, WV, C);
    gather_kernel<<<dim3(NN, VV), 128>>>(out);
}